// round 2
// baseline (speedup 1.0000x reference)
#include <cuda_runtime.h>

// Problem constants
#define NN 50000
#define NE 800000
#define F0 100
#define F1 256
#define F2 128

// ---------------- scratch (no allocations allowed -> device globals) ----------
__device__ float g_deg[NN];
__device__ float g_dinv[NN];
__device__ float g_G1[(size_t)NN * F1];   // dinv-scaled X@W1
__device__ float g_ACC1[(size_t)NN * F1]; // aggregation accumulator layer 1
__device__ float g_X2[(size_t)NN * F1];   // relu output of layer 1
__device__ float g_G2[(size_t)NN * F2];
__device__ float g_ACC2[(size_t)NN * F2];
__device__ int   g_is64;                  // edge_index dtype flag

// ---------------- edge-index dtype detection (int64 vs int32) -----------------
__global__ void detect_idx_kernel(const void* ei) {
    if (blockIdx.x == 0 && threadIdx.x == 0) {
        const long long* p = (const long long*)ei;
        int ok = 1;
        for (int i = 0; i < 256; i++) {      // stays within smallest possible buffer
            long long v = p[i];
            if (v < 0 || v >= NN) { ok = 0; break; }
        }
        g_is64 = ok;
    }
}

__device__ __forceinline__ int edge_at(const void* ei, int which, int e) {
    if (g_is64) return (int)((const long long*)ei)[(size_t)which * NE + e];
    return ((const int*)ei)[(size_t)which * NE + e];
}

// ---------------- degree / dinv ------------------------------------------------
__global__ void deg_init_kernel() {
    int i = blockIdx.x * blockDim.x + threadIdx.x;
    if (i < NN) g_deg[i] = 1.0f;  // self-loop
}

__global__ void deg_count_kernel(const void* __restrict__ ei) {
    int e = blockIdx.x * blockDim.x + threadIdx.x;
    if (e < NE) atomicAdd(&g_deg[edge_at(ei, 1, e)], 1.0f);
}

__global__ void dinv_kernel() {
    int i = blockIdx.x * blockDim.x + threadIdx.x;
    if (i < NN) g_dinv[i] = rsqrtf(g_deg[i]);
}

// ---------------- SGEMM with dinv row-scale epilogue ---------------------------
// C = (A @ B) * dinv[row], written to both G and ACC.
// A: MxK row-major, B: KxN row-major. BM=64, BN=64, BK=16, 256 threads, 4x4/thread.
template <int BM, int BN, int BK, int TM, int TN>
__global__ void sgemm_scale_kernel(const float* __restrict__ A,
                                   const float* __restrict__ B,
                                   const float* __restrict__ dinv,
                                   float* __restrict__ G,
                                   float* __restrict__ ACC,
                                   int M, int N, int K) {
    __shared__ float As[BK][BM];
    __shared__ float Bs[BK][BN];

    const int tid = threadIdx.x;
    const int tx  = tid % (BN / TN);   // 0..15
    const int ty  = tid / (BN / TN);   // 0..15
    const int row0 = blockIdx.y * BM;
    const int col0 = blockIdx.x * BN;

    float acc[TM][TN];
    #pragma unroll
    for (int i = 0; i < TM; i++)
        #pragma unroll
        for (int j = 0; j < TN; j++) acc[i][j] = 0.0f;

    for (int k0 = 0; k0 < K; k0 += BK) {
        // load A tile (transposed into As[k][m])
        #pragma unroll
        for (int e = tid; e < BM * BK; e += BM * BN / (TM * TN)) {
            int m = e / BK, k = e % BK;
            float v = 0.0f;
            if (row0 + m < M && k0 + k < K)
                v = A[(size_t)(row0 + m) * K + k0 + k];
            As[k][m] = v;
        }
        // load B tile
        #pragma unroll
        for (int e = tid; e < BK * BN; e += BM * BN / (TM * TN)) {
            int k = e / BN, n = e % BN;
            float v = 0.0f;
            if (k0 + k < K)
                v = B[(size_t)(k0 + k) * N + col0 + n];
            Bs[k][n] = v;
        }
        __syncthreads();

        #pragma unroll
        for (int k = 0; k < BK; k++) {
            float a[TM], b[TN];
            #pragma unroll
            for (int i = 0; i < TM; i++) a[i] = As[k][ty * TM + i];
            #pragma unroll
            for (int j = 0; j < TN; j++) b[j] = Bs[k][tx * TN + j];
            #pragma unroll
            for (int i = 0; i < TM; i++)
                #pragma unroll
                for (int j = 0; j < TN; j++)
                    acc[i][j] += a[i] * b[j];
        }
        __syncthreads();
    }

    #pragma unroll
    for (int i = 0; i < TM; i++) {
        int r = row0 + ty * TM + i;
        if (r >= M) continue;
        float s = dinv[r];
        #pragma unroll
        for (int j = 0; j < TN; j++) {
            int c = col0 + tx * TN + j;   // N multiple of BN -> no col guard
            float v = acc[i][j] * s;
            G[(size_t)r * N + c]   = v;
            ACC[(size_t)r * N + c] = v;
        }
    }
}

// ---------------- per-edge scatter: ACC[dst] += G[src] -------------------------
// One thread per (edge, float4-chunk). LOGC = log2(F/4).
template <int LOGC>
__global__ void scatter_kernel(const void* __restrict__ ei,
                               const float* __restrict__ G,
                               float* __restrict__ ACC) {
    const int F = 4 << LOGC;
    long long idx = (long long)blockIdx.x * blockDim.x + threadIdx.x;
    const long long total = (long long)NE << LOGC;
    if (idx >= total) return;
    int e = (int)(idx >> LOGC);
    int j = (int)(idx & ((1 << LOGC) - 1));
    int s = edge_at(ei, 0, e);
    int d = edge_at(ei, 1, e);
    float4 v = ((const float4*)(G + (size_t)s * F))[j];
    float* p = ACC + (size_t)d * F + 4 * j;
    atomicAdd(p + 0, v.x);
    atomicAdd(p + 1, v.y);
    atomicAdd(p + 2, v.z);
    atomicAdd(p + 3, v.w);
}

// ---------------- layer epilogue: X = relu(dinv[row]*ACC + b[col]) ------------
template <int LOGF>
__global__ void relu_epilogue_kernel(const float* __restrict__ ACC,
                                     const float* __restrict__ b,
                                     float* __restrict__ X) {
    long long i = (long long)blockIdx.x * blockDim.x + threadIdx.x;
    const long long total = (long long)NN << LOGF;
    if (i >= total) return;
    int r = (int)(i >> LOGF);
    int c = (int)(i & ((1 << LOGF) - 1));
    X[i] = fmaxf(g_dinv[r] * ACC[i] + b[c], 0.0f);
}

// ---------------- final: out[i] = sum_f relu(dinv*ACC2+b2) * Wfc + bfc --------
__global__ void final_kernel(const float* __restrict__ ACC2,
                             const float* __restrict__ b2,
                             const float* __restrict__ Wfc,
                             const float* __restrict__ bfc,
                             float* __restrict__ out) {
    int w    = (blockIdx.x * blockDim.x + threadIdx.x) >> 5;
    int lane = threadIdx.x & 31;
    if (w >= NN) return;
    float di  = g_dinv[w];
    float sum = 0.0f;
    #pragma unroll
    for (int f = lane; f < F2; f += 32)
        sum += fmaxf(di * ACC2[(size_t)w * F2 + f] + b2[f], 0.0f) * Wfc[f];
    #pragma unroll
    for (int o = 16; o; o >>= 1) sum += __shfl_down_sync(0xffffffffu, sum, o);
    if (lane == 0) out[w] = sum + bfc[0];
}

// ---------------- launch --------------------------------------------------------
extern "C" void kernel_launch(void* const* d_in, const int* in_sizes, int n_in,
                              void* d_out, int out_size) {
    const float* x   = (const float*)d_in[0];
    const void*  ei  = d_in[1];             // int64 or int32, detected on device
    const float* W1  = (const float*)d_in[2];
    const float* b1  = (const float*)d_in[3];
    const float* W2  = (const float*)d_in[4];
    const float* b2  = (const float*)d_in[5];
    const float* Wfc = (const float*)d_in[6];
    const float* bfc = (const float*)d_in[7];
    float*       out = (float*)d_out;

    float *deg, *dinv, *G1, *ACC1, *X2, *G2, *ACC2;
    cudaGetSymbolAddress((void**)&deg,  g_deg);
    cudaGetSymbolAddress((void**)&dinv, g_dinv);
    cudaGetSymbolAddress((void**)&G1,   g_G1);
    cudaGetSymbolAddress((void**)&ACC1, g_ACC1);
    cudaGetSymbolAddress((void**)&X2,   g_X2);
    cudaGetSymbolAddress((void**)&G2,   g_G2);
    cudaGetSymbolAddress((void**)&ACC2, g_ACC2);

    detect_idx_kernel<<<1, 32>>>(ei);

    deg_init_kernel<<<(NN + 255) / 256, 256>>>();
    deg_count_kernel<<<(NE + 255) / 256, 256>>>(ei);
    dinv_kernel<<<(NN + 255) / 256, 256>>>();

    // layer 1: G1 = dinv * (x @ W1); ACC1 = G1
    {
        dim3 grid(F1 / 64, (NN + 63) / 64);
        sgemm_scale_kernel<64, 64, 16, 4, 4><<<grid, 256>>>(x, W1, dinv, G1, ACC1,
                                                            NN, F1, F0);
    }
    {
        long long total = (long long)NE * (F1 / 4);
        scatter_kernel<6><<<(unsigned)((total + 255) / 256), 256>>>(ei, G1, ACC1);
    }
    {
        long long total = (long long)NN * F1;
        relu_epilogue_kernel<8><<<(unsigned)((total + 255) / 256), 256>>>(ACC1, b1, X2);
    }

    // layer 2: G2 = dinv * (X2 @ W2); ACC2 = G2
    {
        dim3 grid(F2 / 64, (NN + 63) / 64);
        sgemm_scale_kernel<64, 64, 16, 4, 4><<<grid, 256>>>(X2, W2, dinv, G2, ACC2,
                                                            NN, F2, F1);
    }
    {
        long long total = (long long)NE * (F2 / 4);
        scatter_kernel<5><<<(unsigned)((total + 255) / 256), 256>>>(ei, G2, ACC2);
    }

    // final epilogue + FC fused
    final_kernel<<<(NN * 32 + 255) / 256, 256>>>(ACC2, b2, Wfc, bfc, out);
}

// round 3
// speedup vs baseline: 1.8613x; 1.8613x over previous
#include <cuda_runtime.h>

#define NN 50000
#define NE 800000
#define F0 100
#define F1 256
#define F2 128

// ---------------- scratch (device globals; no allocations allowed) -------------
__device__ float g_dinv[NN];
__device__ int   g_cnt[NN];          // histogram, then reused as fill cursor
__device__ int   g_rowptr[NN + 1];
__device__ int   g_csr_src[NE];      // src ids grouped by dst
__device__ float g_G1[(size_t)NN * F1];
__device__ float g_X2[(size_t)NN * F1];
__device__ float g_G2[(size_t)NN * F2];
__device__ int   g_is64;

// ---------------- edge-index dtype detection (int64 vs int32) ------------------
__global__ void detect_idx_kernel(const void* ei) {
    if (threadIdx.x == 0) {
        const long long* p = (const long long*)ei;
        int ok = 1;
        for (int i = 0; i < 256; i++) {
            long long v = p[i];
            if (v < 0 || v >= NN) { ok = 0; break; }
        }
        g_is64 = ok;
    }
}

__device__ __forceinline__ int edge_at(const void* ei, int which, int e) {
    if (g_is64) return (int)((const long long*)ei)[(size_t)which * NE + e];
    return ((const int*)ei)[(size_t)which * NE + e];
}

// ---------------- CSR build -----------------------------------------------------
__global__ void zero_cnt_kernel() {
    int i = blockIdx.x * blockDim.x + threadIdx.x;
    if (i < NN) g_cnt[i] = 0;
}

__global__ void hist_kernel(const void* __restrict__ ei) {
    int e = blockIdx.x * blockDim.x + threadIdx.x;
    if (e < NE) atomicAdd(&g_cnt[edge_at(ei, 1, e)], 1);
}

__global__ void dinv_kernel() {
    int i = blockIdx.x * blockDim.x + threadIdx.x;
    if (i < NN) g_dinv[i] = rsqrtf((float)(g_cnt[i] + 1));  // +1 self-loop
}

// single-block exclusive scan of g_cnt -> g_rowptr
__global__ void scan_kernel() {
    __shared__ int partial[1024];
    __shared__ int carry_s;
    const int tid = threadIdx.x;
    if (tid == 0) carry_s = 0;
    __syncthreads();
    for (int base = 0; base < NN; base += 1024) {
        int v = (base + tid < NN) ? g_cnt[base + tid] : 0;
        partial[tid] = v;
        __syncthreads();
        #pragma unroll
        for (int o = 1; o < 1024; o <<= 1) {
            int t = (tid >= o) ? partial[tid - o] : 0;
            __syncthreads();
            partial[tid] += t;
            __syncthreads();
        }
        int incl  = partial[tid];
        int total = partial[1023];
        int carry = carry_s;
        if (base + tid < NN) g_rowptr[base + tid] = carry + incl - v;
        __syncthreads();
        if (tid == 0) carry_s = carry + total;
        __syncthreads();
    }
    if (tid == 0) g_rowptr[NN] = carry_s;
}

__global__ void fill_csr_kernel(const void* __restrict__ ei) {
    int e = blockIdx.x * blockDim.x + threadIdx.x;
    if (e >= NE) return;
    int s = edge_at(ei, 0, e);
    int d = edge_at(ei, 1, e);
    int pos = g_rowptr[d] + atomicAdd(&g_cnt[d], 1);
    g_csr_src[pos] = s;
}

// ---------------- SGEMM: G = dinv[row] * (A @ B) --------------------------------
// BM=128, BN=64, BK=16, 256 threads, 8x4 per thread.
template <int BM, int BN, int BK, int TM, int TN>
__global__ void sgemm_scale_kernel(const float* __restrict__ A,
                                   const float* __restrict__ B,
                                   const float* __restrict__ dinv,
                                   float* __restrict__ G,
                                   int M, int N, int K) {
    __shared__ float As[BK][BM + 1];
    __shared__ float Bs[BK][BN];

    const int tid  = threadIdx.x;
    const int tx   = tid % (BN / TN);   // 0..15
    const int ty   = tid / (BN / TN);   // 0..15
    const int row0 = blockIdx.y * BM;
    const int col0 = blockIdx.x * BN;
    const int NT   = (BM / TM) * (BN / TN);  // 256

    float acc[TM][TN];
    #pragma unroll
    for (int i = 0; i < TM; i++)
        #pragma unroll
        for (int j = 0; j < TN; j++) acc[i][j] = 0.0f;

    for (int k0 = 0; k0 < K; k0 += BK) {
        #pragma unroll
        for (int e = tid; e < BM * BK; e += NT) {
            int m = e / BK, k = e % BK;
            float v = 0.0f;
            if (row0 + m < M && k0 + k < K)
                v = A[(size_t)(row0 + m) * K + k0 + k];
            As[k][m] = v;
        }
        #pragma unroll
        for (int e = tid; e < BK * BN; e += NT) {
            int k = e / BN, n = e % BN;
            float v = 0.0f;
            if (k0 + k < K)
                v = B[(size_t)(k0 + k) * N + col0 + n];
            Bs[k][n] = v;
        }
        __syncthreads();

        #pragma unroll
        for (int k = 0; k < BK; k++) {
            float a[TM], b[TN];
            #pragma unroll
            for (int i = 0; i < TM; i++) a[i] = As[k][ty * TM + i];
            #pragma unroll
            for (int j = 0; j < TN; j++) b[j] = Bs[k][tx * TN + j];
            #pragma unroll
            for (int i = 0; i < TM; i++)
                #pragma unroll
                for (int j = 0; j < TN; j++)
                    acc[i][j] += a[i] * b[j];
        }
        __syncthreads();
    }

    #pragma unroll
    for (int i = 0; i < TM; i++) {
        int r = row0 + ty * TM + i;
        if (r >= M) continue;
        float s = dinv[r];
        #pragma unroll
        for (int j = 0; j < TN; j++)
            G[(size_t)r * N + col0 + tx * TN + j] = acc[i][j] * s;
    }
}

// ---------------- layer-1 aggregation (CSR, atomic-free) ------------------------
// One block (256 threads) per dst node; thread = one feature of F1.
__global__ void agg1_kernel(const float* __restrict__ G,
                            const float* __restrict__ b,
                            float* __restrict__ X) {
    const int d   = blockIdx.x;
    const int tid = threadIdx.x;
    __shared__ int nbr[256];

    const int beg = g_rowptr[d], end = g_rowptr[d + 1];
    float acc = G[(size_t)d * F1 + tid];        // self-loop term
    for (int c = beg; c < end; c += 256) {
        int cnt = min(256, end - c);
        __syncthreads();
        if (tid < cnt) nbr[tid] = g_csr_src[c + tid];
        __syncthreads();
        int i = 0;
        for (; i + 4 <= cnt; i += 4) {
            float v0 = G[(size_t)nbr[i + 0] * F1 + tid];
            float v1 = G[(size_t)nbr[i + 1] * F1 + tid];
            float v2 = G[(size_t)nbr[i + 2] * F1 + tid];
            float v3 = G[(size_t)nbr[i + 3] * F1 + tid];
            acc += v0 + v1 + v2 + v3;
        }
        for (; i < cnt; i++) acc += G[(size_t)nbr[i] * F1 + tid];
    }
    X[(size_t)d * F1 + tid] = fmaxf(g_dinv[d] * acc + b[tid], 0.0f);
}

// ---------------- layer-2 aggregation + final FC fused --------------------------
// One block (128 threads) per dst node; thread = one feature of F2.
__global__ void agg2_final_kernel(const float* __restrict__ G,
                                  const float* __restrict__ b2,
                                  const float* __restrict__ Wfc,
                                  const float* __restrict__ bfc,
                                  float* __restrict__ out) {
    const int d    = blockIdx.x;
    const int tid  = threadIdx.x;
    const int lane = tid & 31;
    const int wid  = tid >> 5;
    __shared__ int   nbr[128];
    __shared__ float ws[4];

    const int beg = g_rowptr[d], end = g_rowptr[d + 1];
    float acc = G[(size_t)d * F2 + tid];
    for (int c = beg; c < end; c += 128) {
        int cnt = min(128, end - c);
        __syncthreads();
        if (tid < cnt) nbr[tid] = g_csr_src[c + tid];
        __syncthreads();
        int i = 0;
        for (; i + 4 <= cnt; i += 4) {
            float v0 = G[(size_t)nbr[i + 0] * F2 + tid];
            float v1 = G[(size_t)nbr[i + 1] * F2 + tid];
            float v2 = G[(size_t)nbr[i + 2] * F2 + tid];
            float v3 = G[(size_t)nbr[i + 3] * F2 + tid];
            acc += v0 + v1 + v2 + v3;
        }
        for (; i < cnt; i++) acc += G[(size_t)nbr[i] * F2 + tid];
    }
    float h = fmaxf(g_dinv[d] * acc + b2[tid], 0.0f);
    float v = h * Wfc[tid];
    #pragma unroll
    for (int o = 16; o; o >>= 1) v += __shfl_down_sync(0xffffffffu, v, o);
    if (lane == 0) ws[wid] = v;
    __syncthreads();
    if (tid == 0) out[d] = ws[0] + ws[1] + ws[2] + ws[3] + bfc[0];
}

// ---------------- launch ---------------------------------------------------------
extern "C" void kernel_launch(void* const* d_in, const int* in_sizes, int n_in,
                              void* d_out, int out_size) {
    const float* x   = (const float*)d_in[0];
    const void*  ei  = d_in[1];
    const float* W1  = (const float*)d_in[2];
    const float* b1  = (const float*)d_in[3];
    const float* W2  = (const float*)d_in[4];
    const float* b2  = (const float*)d_in[5];
    const float* Wfc = (const float*)d_in[6];
    const float* bfc = (const float*)d_in[7];
    float*       out = (float*)d_out;

    float *dinv, *G1, *X2, *G2;
    cudaGetSymbolAddress((void**)&dinv, g_dinv);
    cudaGetSymbolAddress((void**)&G1,   g_G1);
    cudaGetSymbolAddress((void**)&X2,   g_X2);
    cudaGetSymbolAddress((void**)&G2,   g_G2);

    detect_idx_kernel<<<1, 32>>>(ei);

    // CSR build + dinv
    zero_cnt_kernel<<<(NN + 255) / 256, 256>>>();
    hist_kernel<<<(NE + 255) / 256, 256>>>(ei);
    dinv_kernel<<<(NN + 255) / 256, 256>>>();
    scan_kernel<<<1, 1024>>>();
    zero_cnt_kernel<<<(NN + 255) / 256, 256>>>();
    fill_csr_kernel<<<(NE + 255) / 256, 256>>>(ei);

    // layer 1
    {
        dim3 grid(F1 / 64, (NN + 127) / 128);
        sgemm_scale_kernel<128, 64, 16, 8, 4><<<grid, 256>>>(x, W1, dinv, G1,
                                                             NN, F1, F0);
    }
    agg1_kernel<<<NN, 256>>>(G1, b1, X2);

    // layer 2
    {
        dim3 grid(F2 / 64, (NN + 127) / 128);
        sgemm_scale_kernel<128, 64, 16, 8, 4><<<grid, 256>>>(X2, W2, dinv, G2,
                                                             NN, F2, F1);
    }
    agg2_final_kernel<<<NN, 128>>>(G2, b2, Wfc, bfc, out);
}

// round 5
// speedup vs baseline: 3.0666x; 1.6476x over previous
#include <cuda_runtime.h>
#include <cuda_bf16.h>
#include <cstdint>

#define NN 50000
#define NE 800000
#define F0 100
#define F1 256
#define F2 128
#define KP1 384   // 3*100 padded to /64
#define KP2 768   // 3*256

// ---------------- scratch (device globals) -------------------------------------
__device__ float g_dinv[NN];
__device__ int   g_cnt[NN];
__device__ int   g_rowptr[NN + 1];
__device__ int   g_csr_src[NE];
__device__ int   g_excl[NN];
__device__ int   g_blocksum[64];
__device__ int   g_blockoff[64];
__device__ __nv_bfloat16 g_A1[(size_t)NN * KP1];
__device__ __nv_bfloat16 g_A2[(size_t)NN * KP2];
__device__ __nv_bfloat16 g_B1[(size_t)F1 * KP1];
__device__ __nv_bfloat16 g_B2[(size_t)F2 * KP2];
__device__ float g_G1[(size_t)NN * F1];
__device__ float g_G2[(size_t)NN * F2];
__device__ int   g_is64;

// ---------------- edge-index dtype ----------------------------------------------
__global__ void detect_idx_kernel(const void* ei) {
    if (threadIdx.x == 0) {
        const long long* p = (const long long*)ei;
        int ok = 1;
        for (int i = 0; i < 256; i++) {
            long long v = p[i];
            if (v < 0 || v >= NN) { ok = 0; break; }
        }
        g_is64 = ok;
    }
}
__device__ __forceinline__ int edge_at(const void* ei, int which, int e) {
    if (g_is64) return (int)((const long long*)ei)[(size_t)which * NE + e];
    return ((const int*)ei)[(size_t)which * NE + e];
}

// ---------------- CSR build ------------------------------------------------------
__global__ void zero_cnt_kernel() {
    int i = blockIdx.x * blockDim.x + threadIdx.x;
    if (i < NN) g_cnt[i] = 0;
}
__global__ void hist_kernel(const void* __restrict__ ei) {
    int e = blockIdx.x * blockDim.x + threadIdx.x;
    if (e < NE) atomicAdd(&g_cnt[edge_at(ei, 1, e)], 1);
}
__global__ void dinv_kernel() {
    int i = blockIdx.x * blockDim.x + threadIdx.x;
    if (i < NN) g_dinv[i] = rsqrtf((float)(g_cnt[i] + 1));
}
__global__ void scan_block_kernel() {  // grid 49, block 1024
    __shared__ int wsum[32];
    int t = threadIdx.x, lane = t & 31, w = t >> 5;
    int i = blockIdx.x * 1024 + t;
    int v = (i < NN) ? g_cnt[i] : 0;
    int incl = v;
    #pragma unroll
    for (int o = 1; o < 32; o <<= 1) {
        int n = __shfl_up_sync(~0u, incl, o);
        if (lane >= o) incl += n;
    }
    if (lane == 31) wsum[w] = incl;
    __syncthreads();
    if (w == 0) {
        int s = wsum[lane];
        #pragma unroll
        for (int o = 1; o < 32; o <<= 1) {
            int n = __shfl_up_sync(~0u, s, o);
            if (lane >= o) s += n;
        }
        wsum[lane] = s;
    }
    __syncthreads();
    incl += (w > 0) ? wsum[w - 1] : 0;
    if (i < NN) g_excl[i] = incl - v;
    if (t == 1023) g_blocksum[blockIdx.x] = incl;
}
__global__ void scan_sums_kernel(int nb) {  // 1 block, 64 threads
    __shared__ int ws[2];
    int t = threadIdx.x, lane = t & 31, w = t >> 5;
    int v = (t < nb) ? g_blocksum[t] : 0;
    int incl = v;
    #pragma unroll
    for (int o = 1; o < 32; o <<= 1) {
        int n = __shfl_up_sync(~0u, incl, o);
        if (lane >= o) incl += n;
    }
    if (lane == 31) ws[w] = incl;
    __syncthreads();
    incl += (w > 0) ? ws[0] : 0;
    if (t < nb) g_blockoff[t] = incl - v;
    if (t == nb - 1) g_rowptr[NN] = incl;
}
__global__ void scan_add_kernel() {
    int i = blockIdx.x * blockDim.x + threadIdx.x;
    if (i < NN) g_rowptr[i] = g_excl[i] + g_blockoff[i >> 10];
}
__global__ void fill_csr_kernel(const void* __restrict__ ei) {
    int e = blockIdx.x * blockDim.x + threadIdx.x;
    if (e >= NE) return;
    int s = edge_at(ei, 0, e);
    int d = edge_at(ei, 1, e);
    int pos = g_rowptr[d] + atomicAdd(&g_cnt[d], 1);
    g_csr_src[pos] = s;
}

// ---------------- fp32 -> split-bf16 conversions --------------------------------
__global__ void conv_A1_kernel(const float* __restrict__ x) {
    long long i = (long long)blockIdx.x * blockDim.x + threadIdx.x;
    if (i >= (long long)NN * KP1) return;
    int row = (int)(i / KP1), k = (int)(i % KP1);
    __nv_bfloat16 o = __float2bfloat16(0.0f);
    if (k < 300) {
        int kk = (k < 100) ? k : ((k < 200) ? k - 100 : k - 200);
        float v = x[(size_t)row * F0 + kk];
        __nv_bfloat16 hi = __float2bfloat16(v);
        o = (k >= 100 && k < 200) ? __float2bfloat16(v - __bfloat162float(hi)) : hi;
    }
    g_A1[i] = o;
}
__global__ void conv_W1_kernel(const float* __restrict__ W) {  // [100,256] -> [256][384]
    long long i = (long long)blockIdx.x * blockDim.x + threadIdx.x;
    if (i >= (long long)F1 * KP1) return;
    int n = (int)(i / KP1), k = (int)(i % KP1);
    __nv_bfloat16 o = __float2bfloat16(0.0f);
    if (k < 300) {
        int kk = (k < 100) ? k : ((k < 200) ? k - 100 : k - 200);
        float v = W[(size_t)kk * F1 + n];
        __nv_bfloat16 hi = __float2bfloat16(v);
        o = (k >= 200) ? __float2bfloat16(v - __bfloat162float(hi)) : hi;  // [hi|hi|lo]
    }
    g_B1[i] = o;
}
__global__ void conv_W2_kernel(const float* __restrict__ W) {  // [256,128] -> [128][768]
    long long i = (long long)blockIdx.x * blockDim.x + threadIdx.x;
    if (i >= (long long)F2 * KP2) return;
    int n = (int)(i / KP2), k = (int)(i % KP2);
    int kk = k & 255, seg = k >> 8;
    float v = W[(size_t)kk * F2 + n];
    __nv_bfloat16 hi = __float2bfloat16(v);
    g_B2[i] = (seg == 2) ? __float2bfloat16(v - __bfloat162float(hi)) : hi;
}

// ---------------- mma.sync bf16 GEMM: G = dinv[row] * (A' @ B'^T) ---------------
// A': [M][KP] bf16 K-major. B': [NT][KP] bf16 K-major (= col-major B for mma).
// Block tile 128x128, 4 warps (2x2) of 64x64, K chunk 64. SMEM u32 pitch 36
// (bank = (4r+c) mod 32 -> conflict-free fragment lds).
__device__ __forceinline__ void mma16816(float* c, const uint32_t* a, const uint32_t* b) {
    asm volatile(
        "mma.sync.aligned.m16n8k16.row.col.f32.bf16.bf16.f32 "
        "{%0,%1,%2,%3}, {%4,%5,%6,%7}, {%8,%9}, {%0,%1,%2,%3};"
        : "+f"(c[0]), "+f"(c[1]), "+f"(c[2]), "+f"(c[3])
        : "r"(a[0]), "r"(a[1]), "r"(a[2]), "r"(a[3]), "r"(b[0]), "r"(b[1]));
}

template <int KP, int NT>
__global__ void __launch_bounds__(128)
gemm_mma_kernel(const __nv_bfloat16* __restrict__ A,
                const __nv_bfloat16* __restrict__ B,
                const float* __restrict__ dinv,
                float* __restrict__ G, int M) {
    __shared__ uint32_t As[128][36];
    __shared__ uint32_t Bs[128][36];

    const int tid  = threadIdx.x;
    const int lane = tid & 31;
    const int wid  = tid >> 5;
    const int wr   = wid >> 1;          // 0..1
    const int wc   = wid & 1;           // 0..1
    const int row0 = blockIdx.x * 128;
    const int n0   = blockIdx.y * 128;

    float acc[4][8][4];
    #pragma unroll
    for (int mi = 0; mi < 4; mi++)
        #pragma unroll
        for (int ni = 0; ni < 8; ni++)
            #pragma unroll
            for (int j = 0; j < 4; j++) acc[mi][ni][j] = 0.0f;

    const int seg  = tid & 7;           // uint4 segment within 128B row-chunk
    const int rb   = tid >> 3;          // 0..15

    for (int c = 0; c < KP / 64; c++) {
        const int k0 = c * 64;
        // load A chunk: 128 rows x 64 bf16
        #pragma unroll
        for (int p = 0; p < 8; p++) {
            int r  = rb + p * 16;
            int gr = row0 + r; if (gr >= M) gr = M - 1;
            uint4 v = ((const uint4*)(A + (size_t)gr * KP + k0))[seg];
            uint32_t* d = &As[r][seg * 4];
            d[0] = v.x; d[1] = v.y; d[2] = v.z; d[3] = v.w;
        }
        // load B chunk: 128 rows x 64 bf16
        #pragma unroll
        for (int p = 0; p < 8; p++) {
            int r = rb + p * 16;
            uint4 v = ((const uint4*)(B + (size_t)(n0 + r) * KP + k0))[seg];
            uint32_t* d = &Bs[r][seg * 4];
            d[0] = v.x; d[1] = v.y; d[2] = v.z; d[3] = v.w;
        }
        __syncthreads();

        #pragma unroll
        for (int ks = 0; ks < 4; ks++) {
            const int kc = ks * 8 + (lane & 3);
            const int q  = lane >> 2;
            uint32_t a[4][4], b[8][2];
            #pragma unroll
            for (int mi = 0; mi < 4; mi++) {
                int ar = wr * 64 + mi * 16 + q;
                a[mi][0] = As[ar][kc];
                a[mi][1] = As[ar + 8][kc];
                a[mi][2] = As[ar][kc + 4];
                a[mi][3] = As[ar + 8][kc + 4];
            }
            #pragma unroll
            for (int ni = 0; ni < 8; ni++) {
                int br = wc * 64 + ni * 8 + q;
                b[ni][0] = Bs[br][kc];
                b[ni][1] = Bs[br][kc + 4];
            }
            #pragma unroll
            for (int mi = 0; mi < 4; mi++)
                #pragma unroll
                for (int ni = 0; ni < 8; ni++)
                    mma16816(acc[mi][ni], a[mi], b[ni]);
        }
        __syncthreads();
    }

    // epilogue: scale by dinv[row], write fp32
    const int q  = lane >> 2;
    const int cp = (lane & 3) * 2;
    #pragma unroll
    for (int mi = 0; mi < 4; mi++) {
        int r0g = row0 + wr * 64 + mi * 16 + q;
        #pragma unroll
        for (int half = 0; half < 2; half++) {
            int r = r0g + half * 8;
            if (r >= M) continue;
            float s = dinv[r];
            float* rowp = G + (size_t)r * NT + n0 + wc * 64;
            #pragma unroll
            for (int ni = 0; ni < 8; ni++) {
                float2 v;
                v.x = acc[mi][ni][half * 2 + 0] * s;
                v.y = acc[mi][ni][half * 2 + 1] * s;
                *(float2*)(rowp + ni * 8 + cp) = v;
            }
        }
    }
}

// ---------------- layer-1 aggregation + split-bf16 conversion fused --------------
__global__ void agg1_kernel(const float* __restrict__ G,
                            const float* __restrict__ b) {
    const int d = blockIdx.x;
    const int tid = threadIdx.x;
    __shared__ int nbr[256];

    const int beg = g_rowptr[d], end = g_rowptr[d + 1];
    float acc = G[(size_t)d * F1 + tid];
    for (int c = beg; c < end; c += 256) {
        int cnt = min(256, end - c);
        __syncthreads();
        if (tid < cnt) nbr[tid] = g_csr_src[c + tid];
        __syncthreads();
        int i = 0;
        for (; i + 4 <= cnt; i += 4) {
            float v0 = G[(size_t)nbr[i + 0] * F1 + tid];
            float v1 = G[(size_t)nbr[i + 1] * F1 + tid];
            float v2 = G[(size_t)nbr[i + 2] * F1 + tid];
            float v3 = G[(size_t)nbr[i + 3] * F1 + tid];
            acc += v0 + v1 + v2 + v3;
        }
        for (; i < cnt; i++) acc += G[(size_t)nbr[i] * F1 + tid];
    }
    float h = fmaxf(g_dinv[d] * acc + b[tid], 0.0f);
    __nv_bfloat16 hi = __float2bfloat16(h);
    __nv_bfloat16 lo = __float2bfloat16(h - __bfloat162float(hi));
    size_t base = (size_t)d * KP2;
    g_A2[base + tid]       = hi;
    g_A2[base + 256 + tid] = lo;
    g_A2[base + 512 + tid] = hi;
}

// ---------------- layer-2 aggregation + final FC fused ---------------------------
__global__ void agg2_final_kernel(const float* __restrict__ G,
                                  const float* __restrict__ b2,
                                  const float* __restrict__ Wfc,
                                  const float* __restrict__ bfc,
                                  float* __restrict__ out) {
    const int d = blockIdx.x;
    const int tid = threadIdx.x;
    const int lane = tid & 31;
    const int wid = tid >> 5;
    __shared__ int nbr[128];
    __shared__ float ws[4];

    const int beg = g_rowptr[d], end = g_rowptr[d + 1];
    float acc = G[(size_t)d * F2 + tid];
    for (int c = beg; c < end; c += 128) {
        int cnt = min(128, end - c);
        __syncthreads();
        if (tid < cnt) nbr[tid] = g_csr_src[c + tid];
        __syncthreads();
        int i = 0;
        for (; i + 4 <= cnt; i += 4) {
            float v0 = G[(size_t)nbr[i + 0] * F2 + tid];
            float v1 = G[(size_t)nbr[i + 1] * F2 + tid];
            float v2 = G[(size_t)nbr[i + 2] * F2 + tid];
            float v3 = G[(size_t)nbr[i + 3] * F2 + tid];
            acc += v0 + v1 + v2 + v3;
        }
        for (; i < cnt; i++) acc += G[(size_t)nbr[i] * F2 + tid];
    }
    float h = fmaxf(g_dinv[d] * acc + b2[tid], 0.0f);
    float v = h * Wfc[tid];
    #pragma unroll
    for (int o = 16; o; o >>= 1) v += __shfl_down_sync(0xffffffffu, v, o);
    if (lane == 0) ws[wid] = v;
    __syncthreads();
    if (tid == 0) out[d] = ws[0] + ws[1] + ws[2] + ws[3] + bfc[0];
}

// ---------------- launch ----------------------------------------------------------
extern "C" void kernel_launch(void* const* d_in, const int* in_sizes, int n_in,
                              void* d_out, int out_size) {
    const float* x   = (const float*)d_in[0];
    const void*  ei  = d_in[1];
    const float* W1  = (const float*)d_in[2];
    const float* b1  = (const float*)d_in[3];
    const float* W2  = (const float*)d_in[4];
    const float* b2  = (const float*)d_in[5];
    const float* Wfc = (const float*)d_in[6];
    const float* bfc = (const float*)d_in[7];
    float*       out = (float*)d_out;

    float *dinv, *G1, *G2;
    __nv_bfloat16 *A1, *A2, *B1, *B2;
    cudaGetSymbolAddress((void**)&dinv, g_dinv);
    cudaGetSymbolAddress((void**)&G1, g_G1);
    cudaGetSymbolAddress((void**)&G2, g_G2);
    cudaGetSymbolAddress((void**)&A1, g_A1);
    cudaGetSymbolAddress((void**)&A2, g_A2);
    cudaGetSymbolAddress((void**)&B1, g_B1);
    cudaGetSymbolAddress((void**)&B2, g_B2);

    detect_idx_kernel<<<1, 32>>>(ei);

    // CSR build + dinv
    zero_cnt_kernel<<<(NN + 255) / 256, 256>>>();
    hist_kernel<<<(NE + 255) / 256, 256>>>(ei);
    dinv_kernel<<<(NN + 255) / 256, 256>>>();
    const int NB = (NN + 1023) / 1024;  // 49
    scan_block_kernel<<<NB, 1024>>>();
    scan_sums_kernel<<<1, 64>>>(NB);
    scan_add_kernel<<<(NN + 255) / 256, 256>>>();
    zero_cnt_kernel<<<(NN + 255) / 256, 256>>>();
    fill_csr_kernel<<<(NE + 255) / 256, 256>>>(ei);

    // conversions
    {
        long long t1 = (long long)NN * KP1;
        conv_A1_kernel<<<(unsigned)((t1 + 255) / 256), 256>>>(x);
        long long tw1 = (long long)F1 * KP1;
        conv_W1_kernel<<<(unsigned)((tw1 + 255) / 256), 256>>>(W1);
        long long tw2 = (long long)F2 * KP2;
        conv_W2_kernel<<<(unsigned)((tw2 + 255) / 256), 256>>>(W2);
    }

    const int MT = (NN + 127) / 128;  // 391

    // layer 1: G1 = dinv * (A1' @ B1'^T)   [N=256 -> grid.y=2]
    {
        dim3 grid(MT, F1 / 128);
        gemm_mma_kernel<KP1, F1><<<grid, 128>>>(A1, B1, dinv, G1, NN);
    }
    agg1_kernel<<<NN, 256>>>(G1, b1);

    // layer 2: G2 = dinv * (A2' @ B2'^T)   [N=128 -> grid.y=1]
    {
        dim3 grid(MT, F2 / 128);
        gemm_mma_kernel<KP2, F2><<<grid, 128>>>(A2, B2, dinv, G2, NN);
    }
    agg2_final_kernel<<<NN, 128>>>(G2, b2, Wfc, bfc, out);
}

// round 6
// speedup vs baseline: 3.8215x; 1.2462x over previous
#include <cuda_runtime.h>
#include <cuda_bf16.h>
#include <cstdint>

#define NN 50000
#define NE 800000
#define F0 100
#define F1 256
#define F2 128
#define KP1 384   // 3*100 padded to /64
#define KP2 768   // 3*256
#define XP 128    // padded xs row

// ---------------- scratch (device globals) -------------------------------------
__device__ float g_dinv[NN];
__device__ int   g_cnt[NN];
__device__ int   g_rowptr[NN + 1];
__device__ int   g_csr_src[NE];
__device__ int   g_excl[NN];
__device__ int   g_blocksum[64];
__device__ int   g_blockoff[64];
__device__ float g_xs[(size_t)NN * XP];                 // dinv-scaled, padded x
__device__ __nv_bfloat16 g_A1[(size_t)NN * KP1];        // split Z = dinv*aggY
__device__ __nv_bfloat16 g_A2[(size_t)NN * KP2];        // split relu(h1)
__device__ __nv_bfloat16 g_B1[(size_t)F1 * KP1];
__device__ __nv_bfloat16 g_B2[(size_t)F2 * KP2];
__device__ float g_G2[(size_t)NN * F2];
__device__ int   g_is64;

// ---------------- edge-index dtype ----------------------------------------------
__global__ void detect_idx_kernel(const void* ei) {
    if (threadIdx.x == 0) {
        const long long* p = (const long long*)ei;
        int ok = 1;
        for (int i = 0; i < 256; i++) {
            long long v = p[i];
            if (v < 0 || v >= NN) { ok = 0; break; }
        }
        g_is64 = ok;
    }
}
__device__ __forceinline__ int edge_at(const void* ei, int which, int e) {
    if (g_is64) return (int)((const long long*)ei)[(size_t)which * NE + e];
    return ((const int*)ei)[(size_t)which * NE + e];
}

// ---------------- CSR build ------------------------------------------------------
__global__ void zero_cnt_kernel() {
    int i = blockIdx.x * blockDim.x + threadIdx.x;
    if (i < NN) g_cnt[i] = 0;
}
__global__ void hist_kernel(const void* __restrict__ ei) {
    int e = blockIdx.x * blockDim.x + threadIdx.x;
    if (e < NE) atomicAdd(&g_cnt[edge_at(ei, 1, e)], 1);
}
__global__ void dinv_kernel() {
    int i = blockIdx.x * blockDim.x + threadIdx.x;
    if (i < NN) g_dinv[i] = rsqrtf((float)(g_cnt[i] + 1));
}
__global__ void scan_block_kernel() {  // grid 49, block 1024
    __shared__ int wsum[32];
    int t = threadIdx.x, lane = t & 31, w = t >> 5;
    int i = blockIdx.x * 1024 + t;
    int v = (i < NN) ? g_cnt[i] : 0;
    int incl = v;
    #pragma unroll
    for (int o = 1; o < 32; o <<= 1) {
        int n = __shfl_up_sync(~0u, incl, o);
        if (lane >= o) incl += n;
    }
    if (lane == 31) wsum[w] = incl;
    __syncthreads();
    if (w == 0) {
        int s = wsum[lane];
        #pragma unroll
        for (int o = 1; o < 32; o <<= 1) {
            int n = __shfl_up_sync(~0u, s, o);
            if (lane >= o) s += n;
        }
        wsum[lane] = s;
    }
    __syncthreads();
    incl += (w > 0) ? wsum[w - 1] : 0;
    if (i < NN) g_excl[i] = incl - v;
    if (t == 1023) g_blocksum[blockIdx.x] = incl;
}
__global__ void scan_sums_kernel(int nb) {  // 1 block, 64 threads
    __shared__ int ws[2];
    int t = threadIdx.x, lane = t & 31, w = t >> 5;
    int v = (t < nb) ? g_blocksum[t] : 0;
    int incl = v;
    #pragma unroll
    for (int o = 1; o < 32; o <<= 1) {
        int n = __shfl_up_sync(~0u, incl, o);
        if (lane >= o) incl += n;
    }
    if (lane == 31) ws[w] = incl;
    __syncthreads();
    incl += (w > 0) ? ws[0] : 0;
    if (t < nb) g_blockoff[t] = incl - v;
    if (t == nb - 1) g_rowptr[NN] = incl;
}
__global__ void scan_add_kernel() {   // also re-zeroes cnt for the fill pass
    int i = blockIdx.x * blockDim.x + threadIdx.x;
    if (i < NN) { g_rowptr[i] = g_excl[i] + g_blockoff[i >> 10]; g_cnt[i] = 0; }
}
__global__ void fill_csr_kernel(const void* __restrict__ ei) {
    int e = blockIdx.x * blockDim.x + threadIdx.x;
    if (e >= NE) return;
    int s = edge_at(ei, 0, e);
    int d = edge_at(ei, 1, e);
    int pos = g_rowptr[d] + atomicAdd(&g_cnt[d], 1);
    g_csr_src[pos] = s;
}

// ---------------- xs = dinv * x, padded to 128 cols ------------------------------
__global__ void scale_x_kernel(const float* __restrict__ x) {
    long long i = (long long)blockIdx.x * blockDim.x + threadIdx.x;
    if (i >= (long long)NN * XP) return;
    int r = (int)(i >> 7), c = (int)(i & 127);
    g_xs[i] = (c < F0) ? g_dinv[r] * x[(size_t)r * F0 + c] : 0.0f;
}

// ---------------- weight conversions (split bf16) --------------------------------
__global__ void conv_W1_kernel(const float* __restrict__ W) {  // [100,256] -> [256][384]
    long long i = (long long)blockIdx.x * blockDim.x + threadIdx.x;
    if (i >= (long long)F1 * KP1) return;
    int n = (int)(i / KP1), k = (int)(i % KP1);
    __nv_bfloat16 o = __float2bfloat16(0.0f);
    if (k < 300) {
        int kk = (k < 100) ? k : ((k < 200) ? k - 100 : k - 200);
        float v = W[(size_t)kk * F1 + n];
        __nv_bfloat16 hi = __float2bfloat16(v);
        o = (k >= 200) ? __float2bfloat16(v - __bfloat162float(hi)) : hi;  // [hi|hi|lo]
    }
    g_B1[i] = o;
}
__global__ void conv_W2_kernel(const float* __restrict__ W) {  // [256,128] -> [128][768]
    long long i = (long long)blockIdx.x * blockDim.x + threadIdx.x;
    if (i >= (long long)F2 * KP2) return;
    int n = (int)(i / KP2), k = (int)(i % KP2);
    int kk = k & 255, seg = k >> 8;
    float v = W[(size_t)kk * F2 + n];
    __nv_bfloat16 hi = __float2bfloat16(v);
    g_B2[i] = (seg == 2) ? __float2bfloat16(v - __bfloat162float(hi)) : hi;
}

// ---------------- layer-1 pre-aggregation (CSR) + split-bf16 emit -----------------
// Y[d] = xs[d] + sum_{s in N(d)} xs[s];  Z = dinv[d]*Y;  A1[d] = [hi(Z)|lo(Z)|hi(Z)|0]
__global__ void aggY_kernel() {
    const int d = blockIdx.x;
    const int t = threadIdx.x;          // 128
    __shared__ int nbr[128];

    const int beg = g_rowptr[d], end = g_rowptr[d + 1];
    float acc = g_xs[(size_t)d * XP + t];
    for (int c = beg; c < end; c += 128) {
        int cnt = min(128, end - c);
        __syncthreads();
        if (t < cnt) nbr[t] = g_csr_src[c + t];
        __syncthreads();
        int i = 0;
        for (; i + 4 <= cnt; i += 4) {
            float v0 = g_xs[(size_t)nbr[i + 0] * XP + t];
            float v1 = g_xs[(size_t)nbr[i + 1] * XP + t];
            float v2 = g_xs[(size_t)nbr[i + 2] * XP + t];
            float v3 = g_xs[(size_t)nbr[i + 3] * XP + t];
            acc += v0 + v1 + v2 + v3;
        }
        for (; i < cnt; i++) acc += g_xs[(size_t)nbr[i] * XP + t];
    }
    float z = g_dinv[d] * acc;
    __nv_bfloat16 hi = __float2bfloat16(z);
    __nv_bfloat16 lo = __float2bfloat16(z - __bfloat162float(hi));
    size_t base = (size_t)d * KP1;
    if (t < F0) {
        g_A1[base + t]       = hi;
        g_A1[base + 100 + t] = lo;
        g_A1[base + 200 + t] = hi;
    }
    if (t < 84) g_A1[base + 300 + t] = __float2bfloat16(0.0f);
}

// ---------------- mma.sync bf16 GEMM ---------------------------------------------
// EPI=0: out = dinv[row]*acc -> fp32 G.   EPI=1: relu(acc+bias) -> split-bf16 A2.
__device__ __forceinline__ void mma16816(float* c, const uint32_t* a, const uint32_t* b) {
    asm volatile(
        "mma.sync.aligned.m16n8k16.row.col.f32.bf16.bf16.f32 "
        "{%0,%1,%2,%3}, {%4,%5,%6,%7}, {%8,%9}, {%0,%1,%2,%3};"
        : "+f"(c[0]), "+f"(c[1]), "+f"(c[2]), "+f"(c[3])
        : "r"(a[0]), "r"(a[1]), "r"(a[2]), "r"(a[3]), "r"(b[0]), "r"(b[1]));
}

template <int KP, int NT, int EPI>
__global__ void __launch_bounds__(128)
gemm_mma_kernel(const __nv_bfloat16* __restrict__ A,
                const __nv_bfloat16* __restrict__ B,
                const float* __restrict__ dinv,
                float* __restrict__ G,
                const float* __restrict__ bias,
                __nv_bfloat16* __restrict__ OutB,
                int M) {
    __shared__ uint32_t As[128][36];
    __shared__ uint32_t Bs[128][36];

    const int tid  = threadIdx.x;
    const int lane = tid & 31;
    const int wid  = tid >> 5;
    const int wr   = wid >> 1;
    const int wc   = wid & 1;
    const int row0 = blockIdx.x * 128;
    const int n0   = blockIdx.y * 128;

    float acc[4][8][4];
    #pragma unroll
    for (int mi = 0; mi < 4; mi++)
        #pragma unroll
        for (int ni = 0; ni < 8; ni++)
            #pragma unroll
            for (int j = 0; j < 4; j++) acc[mi][ni][j] = 0.0f;

    const int seg = tid & 7;
    const int rb  = tid >> 3;

    for (int c = 0; c < KP / 64; c++) {
        const int k0 = c * 64;
        #pragma unroll
        for (int p = 0; p < 8; p++) {
            int r  = rb + p * 16;
            int gr = row0 + r; if (gr >= M) gr = M - 1;
            uint4 v = ((const uint4*)(A + (size_t)gr * KP + k0))[seg];
            uint32_t* d = &As[r][seg * 4];
            d[0] = v.x; d[1] = v.y; d[2] = v.z; d[3] = v.w;
        }
        #pragma unroll
        for (int p = 0; p < 8; p++) {
            int r = rb + p * 16;
            uint4 v = ((const uint4*)(B + (size_t)(n0 + r) * KP + k0))[seg];
            uint32_t* d = &Bs[r][seg * 4];
            d[0] = v.x; d[1] = v.y; d[2] = v.z; d[3] = v.w;
        }
        __syncthreads();

        #pragma unroll
        for (int ks = 0; ks < 4; ks++) {
            const int kc = ks * 8 + (lane & 3);
            const int q  = lane >> 2;
            uint32_t a[4][4], b[8][2];
            #pragma unroll
            for (int mi = 0; mi < 4; mi++) {
                int ar = wr * 64 + mi * 16 + q;
                a[mi][0] = As[ar][kc];
                a[mi][1] = As[ar + 8][kc];
                a[mi][2] = As[ar][kc + 4];
                a[mi][3] = As[ar + 8][kc + 4];
            }
            #pragma unroll
            for (int ni = 0; ni < 8; ni++) {
                int br = wc * 64 + ni * 8 + q;
                b[ni][0] = Bs[br][kc];
                b[ni][1] = Bs[br][kc + 4];
            }
            #pragma unroll
            for (int mi = 0; mi < 4; mi++)
                #pragma unroll
                for (int ni = 0; ni < 8; ni++)
                    mma16816(acc[mi][ni], a[mi], b[ni]);
        }
        __syncthreads();
    }

    const int q  = lane >> 2;
    const int cp = (lane & 3) * 2;
    #pragma unroll
    for (int mi = 0; mi < 4; mi++) {
        int r0g = row0 + wr * 64 + mi * 16 + q;
        #pragma unroll
        for (int half = 0; half < 2; half++) {
            int r = r0g + half * 8;
            if (r >= M) continue;
            if (EPI == 0) {
                float s = dinv[r];
                float* rowp = G + (size_t)r * NT + n0 + wc * 64;
                #pragma unroll
                for (int ni = 0; ni < 8; ni++) {
                    float2 v;
                    v.x = acc[mi][ni][half * 2 + 0] * s;
                    v.y = acc[mi][ni][half * 2 + 1] * s;
                    *(float2*)(rowp + ni * 8 + cp) = v;
                }
            } else {
                size_t base = (size_t)r * KP2;
                #pragma unroll
                for (int ni = 0; ni < 8; ni++) {
                    int c0 = n0 + wc * 64 + ni * 8 + cp;
                    float v0 = fmaxf(acc[mi][ni][half * 2 + 0] + bias[c0], 0.0f);
                    float v1 = fmaxf(acc[mi][ni][half * 2 + 1] + bias[c0 + 1], 0.0f);
                    __nv_bfloat16 h0 = __float2bfloat16(v0);
                    __nv_bfloat16 h1 = __float2bfloat16(v1);
                    __nv_bfloat16 l0 = __float2bfloat16(v0 - __bfloat162float(h0));
                    __nv_bfloat16 l1 = __float2bfloat16(v1 - __bfloat162float(h1));
                    __nv_bfloat162 hp; hp.x = h0; hp.y = h1;
                    __nv_bfloat162 lp; lp.x = l0; lp.y = l1;
                    *(__nv_bfloat162*)(OutB + base + c0)       = hp;
                    *(__nv_bfloat162*)(OutB + base + 256 + c0) = lp;
                    *(__nv_bfloat162*)(OutB + base + 512 + c0) = hp;
                }
            }
        }
    }
}

// ---------------- layer-2 aggregation + final FC fused ---------------------------
__global__ void agg2_final_kernel(const float* __restrict__ G,
                                  const float* __restrict__ b2,
                                  const float* __restrict__ Wfc,
                                  const float* __restrict__ bfc,
                                  float* __restrict__ out) {
    const int d = blockIdx.x;
    const int tid = threadIdx.x;
    const int lane = tid & 31;
    const int wid = tid >> 5;
    __shared__ int nbr[128];
    __shared__ float ws[4];

    const int beg = g_rowptr[d], end = g_rowptr[d + 1];
    float acc = G[(size_t)d * F2 + tid];
    for (int c = beg; c < end; c += 128) {
        int cnt = min(128, end - c);
        __syncthreads();
        if (tid < cnt) nbr[tid] = g_csr_src[c + tid];
        __syncthreads();
        int i = 0;
        for (; i + 4 <= cnt; i += 4) {
            float v0 = G[(size_t)nbr[i + 0] * F2 + tid];
            float v1 = G[(size_t)nbr[i + 1] * F2 + tid];
            float v2 = G[(size_t)nbr[i + 2] * F2 + tid];
            float v3 = G[(size_t)nbr[i + 3] * F2 + tid];
            acc += v0 + v1 + v2 + v3;
        }
        for (; i < cnt; i++) acc += G[(size_t)nbr[i] * F2 + tid];
    }
    float h = fmaxf(g_dinv[d] * acc + b2[tid], 0.0f);
    float v = h * Wfc[tid];
    #pragma unroll
    for (int o = 16; o; o >>= 1) v += __shfl_down_sync(0xffffffffu, v, o);
    if (lane == 0) ws[wid] = v;
    __syncthreads();
    if (tid == 0) out[d] = ws[0] + ws[1] + ws[2] + ws[3] + bfc[0];
}

// ---------------- launch ----------------------------------------------------------
extern "C" void kernel_launch(void* const* d_in, const int* in_sizes, int n_in,
                              void* d_out, int out_size) {
    const float* x   = (const float*)d_in[0];
    const void*  ei  = d_in[1];
    const float* W1  = (const float*)d_in[2];
    const float* b1  = (const float*)d_in[3];
    const float* W2  = (const float*)d_in[4];
    const float* b2  = (const float*)d_in[5];
    const float* Wfc = (const float*)d_in[6];
    const float* bfc = (const float*)d_in[7];
    float*       out = (float*)d_out;

    float *dinv, *G2;
    __nv_bfloat16 *A1, *A2, *B1, *B2;
    float *b1d;
    cudaGetSymbolAddress((void**)&dinv, g_dinv);
    cudaGetSymbolAddress((void**)&G2, g_G2);
    cudaGetSymbolAddress((void**)&A1, g_A1);
    cudaGetSymbolAddress((void**)&A2, g_A2);
    cudaGetSymbolAddress((void**)&B1, g_B1);
    cudaGetSymbolAddress((void**)&B2, g_B2);
    (void)b1d;

    detect_idx_kernel<<<1, 32>>>(ei);

    // CSR build + dinv
    zero_cnt_kernel<<<(NN + 255) / 256, 256>>>();
    hist_kernel<<<(NE + 255) / 256, 256>>>(ei);
    dinv_kernel<<<(NN + 255) / 256, 256>>>();
    const int NB = (NN + 1023) / 1024;  // 49
    scan_block_kernel<<<NB, 1024>>>();
    scan_sums_kernel<<<1, 64>>>(NB);
    scan_add_kernel<<<(NN + 255) / 256, 256>>>();
    fill_csr_kernel<<<(NE + 255) / 256, 256>>>(ei);

    // xs + weight conversions
    {
        long long t = (long long)NN * XP;
        scale_x_kernel<<<(unsigned)((t + 255) / 256), 256>>>(x);
        long long tw1 = (long long)F1 * KP1;
        conv_W1_kernel<<<(unsigned)((tw1 + 255) / 256), 256>>>(W1);
        long long tw2 = (long long)F2 * KP2;
        conv_W2_kernel<<<(unsigned)((tw2 + 255) / 256), 256>>>(W2);
    }

    // layer 1: pre-aggregate (100 feats), then GEMM with relu+split epilogue
    aggY_kernel<<<NN, 128>>>();
    const int MT = (NN + 127) / 128;  // 391
    {
        dim3 grid(MT, F1 / 128);
        gemm_mma_kernel<KP1, F1, 1><<<grid, 128>>>(A1, B1, nullptr, nullptr, b1, A2, NN);
    }

    // layer 2: GEMM (dinv epilogue) then aggregate + FC
    {
        dim3 grid(MT, F2 / 128);
        gemm_mma_kernel<KP2, F2, 0><<<grid, 128>>>(A2, B2, dinv, G2, nullptr, nullptr, NN);
    }
    agg2_final_kernel<<<NN, 128>>>(G2, b2, Wfc, bfc, out);
}

// round 7
// speedup vs baseline: 4.1726x; 1.0919x over previous
#include <cuda_runtime.h>
#include <cuda_bf16.h>
#include <cstdint>

#define NN 50000
#define NE 800000
#define F0 100
#define F1 256
#define F2 128
#define KP1 384   // 3*100 padded to /64
#define KP2 768   // 3*256

// ---------------- scratch (device globals) -------------------------------------
__device__ float g_dinv[NN];
__device__ int   g_cnt[NN];
__device__ int   g_rowptr[NN + 1];
__device__ int   g_csr_src[NE];
__device__ int   g_excl[NN];
__device__ int   g_blocksum[64];
__device__ int   g_blockoff[64];
__device__ float g_xs[(size_t)NN * F0];                 // dinv-scaled x (same layout as x)
__device__ __nv_bfloat16 g_A1[(size_t)NN * KP1];        // split Z = dinv*aggY
__device__ __nv_bfloat16 g_A2[(size_t)NN * KP2];        // split relu(h1)
__device__ __nv_bfloat16 g_B1[(size_t)F1 * KP1];
__device__ __nv_bfloat16 g_B2[(size_t)F2 * KP2];
__device__ float g_G2[(size_t)NN * F2];
__device__ int   g_is64;

// ---------------- helpers -------------------------------------------------------
__device__ __forceinline__ uint32_t smem_u32(const void* p) {
    uint32_t a;
    asm("{ .reg .u64 t; cvta.to.shared.u64 t, %1; cvt.u32.u64 %0, t; }"
        : "=r"(a) : "l"(p));
    return a;
}
__device__ __forceinline__ void cp_async16(uint32_t sa, const void* gp) {
    asm volatile("cp.async.cg.shared.global [%0], [%1], 16;" :: "r"(sa), "l"(gp));
}
__device__ __forceinline__ int edge_at(const void* ei, int which, int e) {
    if (g_is64) return (int)((const long long*)ei)[(size_t)which * NE + e];
    return ((const int*)ei)[(size_t)which * NE + e];
}

// ---------------- k0: zero counters + edge-index dtype detection ----------------
__global__ void zero_detect_kernel(const void* ei) {
    int i = blockIdx.x * blockDim.x + threadIdx.x;
    if (i < NN) g_cnt[i] = 0;
    if (blockIdx.x == 0 && threadIdx.x == 0) {
        const long long* p = (const long long*)ei;
        int ok = 1;
        for (int j = 0; j < 256; j++) {
            long long v = p[j];
            if (v < 0 || v >= NN) { ok = 0; break; }
        }
        g_is64 = ok;
    }
}

// ---------------- k1: degree histogram ------------------------------------------
__global__ void hist_kernel(const void* __restrict__ ei) {
    int e = blockIdx.x * blockDim.x + threadIdx.x;
    if (e < NE) atomicAdd(&g_cnt[edge_at(ei, 1, e)], 1);
}

// ---------------- k2: per-block scan (also emits dinv) --------------------------
__global__ void scan_block_kernel() {  // grid 49, block 1024
    __shared__ int wsum[32];
    int t = threadIdx.x, lane = t & 31, w = t >> 5;
    int i = blockIdx.x * 1024 + t;
    int v = (i < NN) ? g_cnt[i] : 0;
    if (i < NN) g_dinv[i] = rsqrtf((float)(v + 1));
    int incl = v;
    #pragma unroll
    for (int o = 1; o < 32; o <<= 1) {
        int n = __shfl_up_sync(~0u, incl, o);
        if (lane >= o) incl += n;
    }
    if (lane == 31) wsum[w] = incl;
    __syncthreads();
    if (w == 0) {
        int s = wsum[lane];
        #pragma unroll
        for (int o = 1; o < 32; o <<= 1) {
            int n = __shfl_up_sync(~0u, s, o);
            if (lane >= o) s += n;
        }
        wsum[lane] = s;
    }
    __syncthreads();
    incl += (w > 0) ? wsum[w - 1] : 0;
    if (i < NN) g_excl[i] = incl - v;
    if (t == 1023) g_blocksum[blockIdx.x] = incl;
}
__global__ void scan_sums_kernel(int nb) {  // 1 block, 64 threads
    __shared__ int ws[2];
    int t = threadIdx.x, lane = t & 31, w = t >> 5;
    int v = (t < nb) ? g_blocksum[t] : 0;
    int incl = v;
    #pragma unroll
    for (int o = 1; o < 32; o <<= 1) {
        int n = __shfl_up_sync(~0u, incl, o);
        if (lane >= o) incl += n;
    }
    if (lane == 31) ws[w] = incl;
    __syncthreads();
    incl += (w > 0) ? ws[0] : 0;
    if (t < nb) g_blockoff[t] = incl - v;
    if (t == nb - 1) g_rowptr[NN] = incl;
}
__global__ void scan_add_kernel() {   // also re-zeroes cnt for the fill pass
    int i = blockIdx.x * blockDim.x + threadIdx.x;
    if (i < NN) { g_rowptr[i] = g_excl[i] + g_blockoff[i >> 10]; g_cnt[i] = 0; }
}
__global__ void fill_csr_kernel(const void* __restrict__ ei) {
    int e = blockIdx.x * blockDim.x + threadIdx.x;
    if (e >= NE) return;
    int s = edge_at(ei, 0, e);
    int d = edge_at(ei, 1, e);
    int pos = g_rowptr[d] + atomicAdd(&g_cnt[d], 1);
    g_csr_src[pos] = s;
}

// ---------------- k6: prep = scale_x + conv_W1 + conv_W2 ------------------------
__global__ void prep_kernel(const float* __restrict__ x,
                            const float* __restrict__ W1,
                            const float* __restrict__ W2) {
    const long long N0 = (long long)NN * F0;
    const long long N1 = N0 + (long long)F1 * KP1;
    const long long N2 = N1 + (long long)F2 * KP2;
    long long i = (long long)blockIdx.x * blockDim.x + threadIdx.x;
    if (i < N0) {
        int r = (int)(i / F0);
        g_xs[i] = g_dinv[r] * x[i];
    } else if (i < N1) {
        long long j = i - N0;
        int n = (int)(j / KP1), k = (int)(j % KP1);
        __nv_bfloat16 o = __float2bfloat16(0.0f);
        if (k < 300) {
            int kk = (k < 100) ? k : ((k < 200) ? k - 100 : k - 200);
            float v = W1[(size_t)kk * F1 + n];
            __nv_bfloat16 hi = __float2bfloat16(v);
            o = (k >= 200) ? __float2bfloat16(v - __bfloat162float(hi)) : hi;  // [hi|hi|lo]
        }
        g_B1[j] = o;
    } else if (i < N2) {
        long long j = i - N1;
        int n = (int)(j / KP2), k = (int)(j % KP2);
        int kk = k & 255, seg = k >> 8;
        float v = W2[(size_t)kk * F2 + n];
        __nv_bfloat16 hi = __float2bfloat16(v);
        g_B2[j] = (seg == 2) ? __float2bfloat16(v - __bfloat162float(hi)) : hi;
    }
}

// ---------------- k7: layer-1 pre-aggregation + split-bf16 emit ------------------
__global__ void aggY_kernel() {
    const int d = blockIdx.x;
    const int t = threadIdx.x;          // 128
    __shared__ int nbr[128];

    const int beg = g_rowptr[d], end = g_rowptr[d + 1];
    float acc = (t < F0) ? g_xs[(size_t)d * F0 + t] : 0.0f;
    for (int c = beg; c < end; c += 128) {
        int cnt = min(128, end - c);
        __syncthreads();
        if (t < cnt) nbr[t] = g_csr_src[c + t];
        __syncthreads();
        if (t < F0) {
            int i = 0;
            for (; i + 8 <= cnt; i += 8) {
                float v0 = g_xs[(size_t)nbr[i + 0] * F0 + t];
                float v1 = g_xs[(size_t)nbr[i + 1] * F0 + t];
                float v2 = g_xs[(size_t)nbr[i + 2] * F0 + t];
                float v3 = g_xs[(size_t)nbr[i + 3] * F0 + t];
                float v4 = g_xs[(size_t)nbr[i + 4] * F0 + t];
                float v5 = g_xs[(size_t)nbr[i + 5] * F0 + t];
                float v6 = g_xs[(size_t)nbr[i + 6] * F0 + t];
                float v7 = g_xs[(size_t)nbr[i + 7] * F0 + t];
                acc += ((v0 + v1) + (v2 + v3)) + ((v4 + v5) + (v6 + v7));
            }
            for (; i < cnt; i++) acc += g_xs[(size_t)nbr[i] * F0 + t];
        }
    }
    float z = g_dinv[d] * acc;
    __nv_bfloat16 hi = __float2bfloat16(z);
    __nv_bfloat16 lo = __float2bfloat16(z - __bfloat162float(hi));
    size_t base = (size_t)d * KP1;
    if (t < F0) {
        g_A1[base + t]       = hi;
        g_A1[base + 100 + t] = lo;
        g_A1[base + 200 + t] = hi;
    }
    if (t < 84) g_A1[base + 300 + t] = __float2bfloat16(0.0f);
}

// ---------------- mma.sync bf16 GEMM, cp.async double-buffered -------------------
// EPI=0: out = dinv[row]*acc -> fp32 G.   EPI=1: relu(acc+bias) -> split-bf16 A2.
__device__ __forceinline__ void mma16816(float* c, const uint32_t* a, const uint32_t* b) {
    asm volatile(
        "mma.sync.aligned.m16n8k16.row.col.f32.bf16.bf16.f32 "
        "{%0,%1,%2,%3}, {%4,%5,%6,%7}, {%8,%9}, {%0,%1,%2,%3};"
        : "+f"(c[0]), "+f"(c[1]), "+f"(c[2]), "+f"(c[3])
        : "r"(a[0]), "r"(a[1]), "r"(a[2]), "r"(a[3]), "r"(b[0]), "r"(b[1]));
}

template <int KP, int NT, int EPI>
__global__ void __launch_bounds__(128)
gemm_mma_kernel(const __nv_bfloat16* __restrict__ A,
                const __nv_bfloat16* __restrict__ B,
                const float* __restrict__ dinv,
                float* __restrict__ G,
                const float* __restrict__ bias,
                __nv_bfloat16* __restrict__ OutB,
                int M) {
    extern __shared__ uint32_t smem[];
    // layout: As[2][128][36], Bs[2][128][36]
    uint32_t (*As)[128][36] = (uint32_t (*)[128][36])smem;
    uint32_t (*Bs)[128][36] = (uint32_t (*)[128][36])(smem + 2 * 128 * 36);

    const int tid  = threadIdx.x;
    const int lane = tid & 31;
    const int wid  = tid >> 5;
    const int wr   = wid >> 1;
    const int wc   = wid & 1;
    const int row0 = blockIdx.x * 128;
    const int n0   = blockIdx.y * 128;
    const int seg  = tid & 7;
    const int rb   = tid >> 3;
    constexpr int NC = KP / 64;

    float acc[4][8][4];
    #pragma unroll
    for (int mi = 0; mi < 4; mi++)
        #pragma unroll
        for (int ni = 0; ni < 8; ni++)
            #pragma unroll
            for (int j = 0; j < 4; j++) acc[mi][ni][j] = 0.0f;

    auto load_chunk = [&](int c, int buf) {
        const int k0 = c * 64 + seg * 8;
        #pragma unroll
        for (int p = 0; p < 8; p++) {
            int r  = rb + p * 16;
            int gr = row0 + r; if (gr >= M) gr = M - 1;
            cp_async16(smem_u32(&As[buf][r][seg * 4]), A + (size_t)gr * KP + k0);
        }
        #pragma unroll
        for (int p = 0; p < 8; p++) {
            int r = rb + p * 16;
            cp_async16(smem_u32(&Bs[buf][r][seg * 4]), B + (size_t)(n0 + r) * KP + k0);
        }
        asm volatile("cp.async.commit_group;");
    };

    load_chunk(0, 0);

    for (int c = 0; c < NC; c++) {
        const int buf = c & 1;
        if (c + 1 < NC) {
            load_chunk(c + 1, (c + 1) & 1);
            asm volatile("cp.async.wait_group 1;");
        } else {
            asm volatile("cp.async.wait_group 0;");
        }
        __syncthreads();

        #pragma unroll
        for (int ks = 0; ks < 4; ks++) {
            const int kc = ks * 8 + (lane & 3);
            const int q  = lane >> 2;
            uint32_t a[4][4], b[8][2];
            #pragma unroll
            for (int mi = 0; mi < 4; mi++) {
                int ar = wr * 64 + mi * 16 + q;
                a[mi][0] = As[buf][ar][kc];
                a[mi][1] = As[buf][ar + 8][kc];
                a[mi][2] = As[buf][ar][kc + 4];
                a[mi][3] = As[buf][ar + 8][kc + 4];
            }
            #pragma unroll
            for (int ni = 0; ni < 8; ni++) {
                int br = wc * 64 + ni * 8 + q;
                b[ni][0] = Bs[buf][br][kc];
                b[ni][1] = Bs[buf][br][kc + 4];
            }
            #pragma unroll
            for (int mi = 0; mi < 4; mi++)
                #pragma unroll
                for (int ni = 0; ni < 8; ni++)
                    mma16816(acc[mi][ni], a[mi], b[ni]);
        }
        __syncthreads();
    }

    const int q  = lane >> 2;
    const int cp = (lane & 3) * 2;
    #pragma unroll
    for (int mi = 0; mi < 4; mi++) {
        int r0g = row0 + wr * 64 + mi * 16 + q;
        #pragma unroll
        for (int half = 0; half < 2; half++) {
            int r = r0g + half * 8;
            if (r >= M) continue;
            if (EPI == 0) {
                float s = dinv[r];
                float* rowp = G + (size_t)r * NT + n0 + wc * 64;
                #pragma unroll
                for (int ni = 0; ni < 8; ni++) {
                    float2 v;
                    v.x = acc[mi][ni][half * 2 + 0] * s;
                    v.y = acc[mi][ni][half * 2 + 1] * s;
                    *(float2*)(rowp + ni * 8 + cp) = v;
                }
            } else {
                size_t base = (size_t)r * KP2;
                #pragma unroll
                for (int ni = 0; ni < 8; ni++) {
                    int c0 = n0 + wc * 64 + ni * 8 + cp;
                    float v0 = fmaxf(acc[mi][ni][half * 2 + 0] + bias[c0], 0.0f);
                    float v1 = fmaxf(acc[mi][ni][half * 2 + 1] + bias[c0 + 1], 0.0f);
                    __nv_bfloat16 h0 = __float2bfloat16(v0);
                    __nv_bfloat16 h1 = __float2bfloat16(v1);
                    __nv_bfloat16 l0 = __float2bfloat16(v0 - __bfloat162float(h0));
                    __nv_bfloat16 l1 = __float2bfloat16(v1 - __bfloat162float(h1));
                    __nv_bfloat162 hp; hp.x = h0; hp.y = h1;
                    __nv_bfloat162 lp; lp.x = l0; lp.y = l1;
                    *(__nv_bfloat162*)(OutB + base + c0)       = hp;
                    *(__nv_bfloat162*)(OutB + base + 256 + c0) = lp;
                    *(__nv_bfloat162*)(OutB + base + 512 + c0) = hp;
                }
            }
        }
    }
}

// ---------------- k10: layer-2 aggregation + final FC fused ----------------------
__global__ void agg2_final_kernel(const float* __restrict__ G,
                                  const float* __restrict__ b2,
                                  const float* __restrict__ Wfc,
                                  const float* __restrict__ bfc,
                                  float* __restrict__ out) {
    const int d = blockIdx.x;
    const int tid = threadIdx.x;
    const int lane = tid & 31;
    const int wid = tid >> 5;
    __shared__ int nbr[128];
    __shared__ float ws[4];

    const int beg = g_rowptr[d], end = g_rowptr[d + 1];
    float acc = G[(size_t)d * F2 + tid];
    for (int c = beg; c < end; c += 128) {
        int cnt = min(128, end - c);
        __syncthreads();
        if (tid < cnt) nbr[tid] = g_csr_src[c + tid];
        __syncthreads();
        int i = 0;
        for (; i + 8 <= cnt; i += 8) {
            float v0 = G[(size_t)nbr[i + 0] * F2 + tid];
            float v1 = G[(size_t)nbr[i + 1] * F2 + tid];
            float v2 = G[(size_t)nbr[i + 2] * F2 + tid];
            float v3 = G[(size_t)nbr[i + 3] * F2 + tid];
            float v4 = G[(size_t)nbr[i + 4] * F2 + tid];
            float v5 = G[(size_t)nbr[i + 5] * F2 + tid];
            float v6 = G[(size_t)nbr[i + 6] * F2 + tid];
            float v7 = G[(size_t)nbr[i + 7] * F2 + tid];
            acc += ((v0 + v1) + (v2 + v3)) + ((v4 + v5) + (v6 + v7));
        }
        for (; i < cnt; i++) acc += G[(size_t)nbr[i] * F2 + tid];
    }
    float h = fmaxf(g_dinv[d] * acc + b2[tid], 0.0f);
    float v = h * Wfc[tid];
    #pragma unroll
    for (int o = 16; o; o >>= 1) v += __shfl_down_sync(0xffffffffu, v, o);
    if (lane == 0) ws[wid] = v;
    __syncthreads();
    if (tid == 0) out[d] = ws[0] + ws[1] + ws[2] + ws[3] + bfc[0];
}

// ---------------- launch ----------------------------------------------------------
extern "C" void kernel_launch(void* const* d_in, const int* in_sizes, int n_in,
                              void* d_out, int out_size) {
    const float* x   = (const float*)d_in[0];
    const void*  ei  = d_in[1];
    const float* W1  = (const float*)d_in[2];
    const float* b1  = (const float*)d_in[3];
    const float* W2  = (const float*)d_in[4];
    const float* b2  = (const float*)d_in[5];
    const float* Wfc = (const float*)d_in[6];
    const float* bfc = (const float*)d_in[7];
    float*       out = (float*)d_out;

    float *dinv, *G2;
    __nv_bfloat16 *A1, *A2, *B1, *B2;
    cudaGetSymbolAddress((void**)&dinv, g_dinv);
    cudaGetSymbolAddress((void**)&G2, g_G2);
    cudaGetSymbolAddress((void**)&A1, g_A1);
    cudaGetSymbolAddress((void**)&A2, g_A2);
    cudaGetSymbolAddress((void**)&B1, g_B1);
    cudaGetSymbolAddress((void**)&B2, g_B2);

    const int SMEM = 4 * 128 * 36 * 4;  // 73728 B (2-buf A + 2-buf B)
    cudaFuncSetAttribute(gemm_mma_kernel<KP1, F1, 1>,
                         cudaFuncAttributeMaxDynamicSharedMemorySize, SMEM);
    cudaFuncSetAttribute(gemm_mma_kernel<KP2, F2, 0>,
                         cudaFuncAttributeMaxDynamicSharedMemorySize, SMEM);

    // CSR build + dinv
    zero_detect_kernel<<<(NN + 255) / 256, 256>>>(ei);
    hist_kernel<<<(NE + 255) / 256, 256>>>(ei);
    const int NB = (NN + 1023) / 1024;  // 49
    scan_block_kernel<<<NB, 1024>>>();
    scan_sums_kernel<<<1, 64>>>(NB);
    scan_add_kernel<<<(NN + 255) / 256, 256>>>();
    fill_csr_kernel<<<(NE + 255) / 256, 256>>>(ei);

    // xs + weight conversions (one kernel)
    {
        long long total = (long long)NN * F0 + (long long)F1 * KP1 + (long long)F2 * KP2;
        prep_kernel<<<(unsigned)((total + 255) / 256), 256>>>(x, W1, W2);
    }

    // layer 1: pre-aggregate (100 feats), then GEMM with relu+split epilogue
    aggY_kernel<<<NN, 128>>>();
    const int MT = (NN + 127) / 128;  // 391
    {
        dim3 grid(MT, F1 / 128);
        gemm_mma_kernel<KP1, F1, 1><<<grid, 128, SMEM>>>(A1, B1, nullptr, nullptr, b1, A2, NN);
    }

    // layer 2: GEMM (dinv epilogue) then aggregate + FC
    {
        dim3 grid(MT, F2 / 128);
        gemm_mma_kernel<KP2, F2, 0><<<grid, 128, SMEM>>>(A2, B2, dinv, G2, nullptr, nullptr, NN);
    }
    agg2_final_kernel<<<NN, 128>>>(G2, b2, Wfc, bfc, out);
}

// round 8
// speedup vs baseline: 4.3979x; 1.0540x over previous
#include <cuda_runtime.h>
#include <cuda_bf16.h>
#include <cstdint>

#define NN 50000
#define NE 800000
#define F0 100
#define F1 256
#define F2 128
#define KP1 320   // [hi(100)|lo(100)|hi(100)|pad(20)]
#define KP2 768   // 3*256

// ---------------- scratch (device globals) -------------------------------------
__device__ float g_dinv[NN];
__device__ int   g_cnt[NN];
__device__ int   g_rowptr[NN + 1];
__device__ int   g_csr_src[NE];
__device__ int   g_excl[NN];
__device__ int   g_blocksum[64];
__device__ __nv_bfloat16 g_A1[(size_t)NN * KP1];        // split Z = dinv*aggY
__device__ __nv_bfloat16 g_A2[(size_t)NN * KP2];        // split relu(h1)
__device__ __nv_bfloat16 g_B1[(size_t)F1 * KP1];
__device__ __nv_bfloat16 g_B2[(size_t)F2 * KP2];
__device__ float g_G2[(size_t)NN * F2];
__device__ int   g_is64;

// ---------------- helpers -------------------------------------------------------
__device__ __forceinline__ uint32_t smem_u32(const void* p) {
    uint32_t a;
    asm("{ .reg .u64 t; cvta.to.shared.u64 t, %1; cvt.u32.u64 %0, t; }"
        : "=r"(a) : "l"(p));
    return a;
}
__device__ __forceinline__ void cp_async16(uint32_t sa, const void* gp) {
    asm volatile("cp.async.cg.shared.global [%0], [%1], 16;" :: "r"(sa), "l"(gp));
}
__device__ __forceinline__ int edge_at(const void* ei, int which, int e) {
    if (g_is64) return (int)((const long long*)ei)[(size_t)which * NE + e];
    return ((const int*)ei)[(size_t)which * NE + e];
}

// ---------------- k0: zero counters + dtype detect + W1/W2 split-bf16 conv ------
__global__ void zero_conv_kernel(const void* ei,
                                 const float* __restrict__ W1,
                                 const float* __restrict__ W2) {
    long long i = (long long)blockIdx.x * blockDim.x + threadIdx.x;
    if (i < NN) g_cnt[i] = 0;
    if (i == 0) {
        const long long* p = (const long long*)ei;
        int ok = 1;
        for (int j = 0; j < 256; j++) {
            long long v = p[j];
            if (v < 0 || v >= NN) { ok = 0; break; }
        }
        g_is64 = ok;
    }
    const long long NW1 = (long long)F1 * KP1;            // 81920
    const long long NW2 = NW1 + (long long)F2 * KP2;      // +98304
    if (i < NW1) {
        int n = (int)(i / KP1), k = (int)(i % KP1);
        __nv_bfloat16 o = __float2bfloat16(0.0f);
        if (k < 300) {
            int kk = (k < 100) ? k : ((k < 200) ? k - 100 : k - 200);
            float v = W1[(size_t)kk * F1 + n];
            __nv_bfloat16 hi = __float2bfloat16(v);
            o = (k >= 200) ? __float2bfloat16(v - __bfloat162float(hi)) : hi;  // [hi|hi|lo]
        }
        g_B1[i] = o;
    } else if (i < NW2) {
        long long j = i - NW1;
        int n = (int)(j / KP2), k = (int)(j % KP2);
        int kk = k & 255, seg = k >> 8;
        float v = W2[(size_t)kk * F2 + n];
        __nv_bfloat16 hi = __float2bfloat16(v);
        g_B2[j] = (seg == 2) ? __float2bfloat16(v - __bfloat162float(hi)) : hi;
    }
}

// ---------------- k1: degree histogram ------------------------------------------
__global__ void hist_kernel(const void* __restrict__ ei) {
    int e = blockIdx.x * blockDim.x + threadIdx.x;
    if (e < NE) atomicAdd(&g_cnt[edge_at(ei, 1, e)], 1);
}

// ---------------- k2: per-block scan (also emits dinv) --------------------------
__global__ void scan_block_kernel() {  // grid 49, block 1024
    __shared__ int wsum[32];
    int t = threadIdx.x, lane = t & 31, w = t >> 5;
    int i = blockIdx.x * 1024 + t;
    int v = (i < NN) ? g_cnt[i] : 0;
    if (i < NN) g_dinv[i] = rsqrtf((float)(v + 1));
    int incl = v;
    #pragma unroll
    for (int o = 1; o < 32; o <<= 1) {
        int n = __shfl_up_sync(~0u, incl, o);
        if (lane >= o) incl += n;
    }
    if (lane == 31) wsum[w] = incl;
    __syncthreads();
    if (w == 0) {
        int s = wsum[lane];
        #pragma unroll
        for (int o = 1; o < 32; o <<= 1) {
            int n = __shfl_up_sync(~0u, s, o);
            if (lane >= o) s += n;
        }
        wsum[lane] = s;
    }
    __syncthreads();
    incl += (w > 0) ? wsum[w - 1] : 0;
    if (i < NN) g_excl[i] = incl - v;
    if (t == 1023) g_blocksum[blockIdx.x] = incl;
}

// ---------------- k3: add block offsets (sums scanned in-block) -----------------
#define NB 49
__global__ void scan_add_kernel() {
    __shared__ int bs[NB];
    int t = threadIdx.x;
    if (t < NB) bs[t] = g_blocksum[t];
    __syncthreads();
    int i = blockIdx.x * blockDim.x + t;
    if (i < NN) {
        int bucket = i >> 10;
        int off = 0;
        for (int j = 0; j < bucket; j++) off += bs[j];
        g_rowptr[i] = g_excl[i] + off;
        g_cnt[i] = 0;                      // re-zero for fill pass
    }
    if (i == 0) {
        int tot = 0;
        for (int j = 0; j < NB; j++) tot += bs[j];
        g_rowptr[NN] = tot;
    }
}

// ---------------- k4: CSR fill ----------------------------------------------------
__global__ void fill_csr_kernel(const void* __restrict__ ei) {
    int e = blockIdx.x * blockDim.x + threadIdx.x;
    if (e >= NE) return;
    int s = edge_at(ei, 0, e);
    int d = edge_at(ei, 1, e);
    int pos = g_rowptr[d] + atomicAdd(&g_cnt[d], 1);
    g_csr_src[pos] = s;
}

// ---------------- k5: layer-1 aggregation (dinv on the fly) + split emit ---------
// Z[d] = dinv[d] * ( dinv[d]*x[d] + sum_s dinv[s]*x[s] );  A1[d] = [hi|lo|hi|0]
__global__ void aggY_kernel(const float* __restrict__ x) {
    const int d = blockIdx.x;
    const int t = threadIdx.x;          // 128
    __shared__ int   nbr[128];
    __shared__ float nds[128];

    const int beg = g_rowptr[d], end = g_rowptr[d + 1];
    const float dd = g_dinv[d];
    float acc = (t < F0) ? dd * x[(size_t)d * F0 + t] : 0.0f;
    for (int c = beg; c < end; c += 128) {
        int cnt = min(128, end - c);
        __syncthreads();
        if (t < cnt) {
            int s = g_csr_src[c + t];
            nbr[t] = s;
            nds[t] = g_dinv[s];
        }
        __syncthreads();
        if (t < F0) {
            int i = 0;
            for (; i + 4 <= cnt; i += 4) {
                float v0 = nds[i + 0] * x[(size_t)nbr[i + 0] * F0 + t];
                float v1 = nds[i + 1] * x[(size_t)nbr[i + 1] * F0 + t];
                float v2 = nds[i + 2] * x[(size_t)nbr[i + 2] * F0 + t];
                float v3 = nds[i + 3] * x[(size_t)nbr[i + 3] * F0 + t];
                acc += (v0 + v1) + (v2 + v3);
            }
            for (; i < cnt; i++) acc += nds[i] * x[(size_t)nbr[i] * F0 + t];
        }
    }
    float z = dd * acc;
    __nv_bfloat16 hi = __float2bfloat16(z);
    __nv_bfloat16 lo = __float2bfloat16(z - __bfloat162float(hi));
    size_t base = (size_t)d * KP1;
    if (t < F0) {
        g_A1[base + t]       = hi;
        g_A1[base + 100 + t] = lo;
        g_A1[base + 200 + t] = hi;
    }
    if (t < KP1 - 300) g_A1[base + 300 + t] = __float2bfloat16(0.0f);
}

// ---------------- mma.sync bf16 GEMM, cp.async double-buffered -------------------
__device__ __forceinline__ void mma16816(float* c, const uint32_t* a, const uint32_t* b) {
    asm volatile(
        "mma.sync.aligned.m16n8k16.row.col.f32.bf16.bf16.f32 "
        "{%0,%1,%2,%3}, {%4,%5,%6,%7}, {%8,%9}, {%0,%1,%2,%3};"
        : "+f"(c[0]), "+f"(c[1]), "+f"(c[2]), "+f"(c[3])
        : "r"(a[0]), "r"(a[1]), "r"(a[2]), "r"(a[3]), "r"(b[0]), "r"(b[1]));
}

template <int KP, int NT, int EPI>
__global__ void __launch_bounds__(128)
gemm_mma_kernel(const __nv_bfloat16* __restrict__ A,
                const __nv_bfloat16* __restrict__ B,
                const float* __restrict__ dinv,
                float* __restrict__ G,
                const float* __restrict__ bias,
                __nv_bfloat16* __restrict__ OutB,
                int M) {
    extern __shared__ uint32_t smem[];
    uint32_t (*As)[128][36] = (uint32_t (*)[128][36])smem;
    uint32_t (*Bs)[128][36] = (uint32_t (*)[128][36])(smem + 2 * 128 * 36);

    const int tid  = threadIdx.x;
    const int lane = tid & 31;
    const int wid  = tid >> 5;
    const int wr   = wid >> 1;
    const int wc   = wid & 1;
    const int row0 = blockIdx.x * 128;
    const int n0   = blockIdx.y * 128;
    const int seg  = tid & 7;
    const int rb   = tid >> 3;
    constexpr int NC = KP / 64;

    float acc[4][8][4];
    #pragma unroll
    for (int mi = 0; mi < 4; mi++)
        #pragma unroll
        for (int ni = 0; ni < 8; ni++)
            #pragma unroll
            for (int j = 0; j < 4; j++) acc[mi][ni][j] = 0.0f;

    auto load_chunk = [&](int c, int buf) {
        const int k0 = c * 64 + seg * 8;
        #pragma unroll
        for (int p = 0; p < 8; p++) {
            int r  = rb + p * 16;
            int gr = row0 + r; if (gr >= M) gr = M - 1;
            cp_async16(smem_u32(&As[buf][r][seg * 4]), A + (size_t)gr * KP + k0);
        }
        #pragma unroll
        for (int p = 0; p < 8; p++) {
            int r = rb + p * 16;
            cp_async16(smem_u32(&Bs[buf][r][seg * 4]), B + (size_t)(n0 + r) * KP + k0);
        }
        asm volatile("cp.async.commit_group;");
    };

    load_chunk(0, 0);

    for (int c = 0; c < NC; c++) {
        const int buf = c & 1;
        if (c + 1 < NC) {
            load_chunk(c + 1, (c + 1) & 1);
            asm volatile("cp.async.wait_group 1;");
        } else {
            asm volatile("cp.async.wait_group 0;");
        }
        __syncthreads();

        #pragma unroll
        for (int ks = 0; ks < 4; ks++) {
            const int kc = ks * 8 + (lane & 3);
            const int q  = lane >> 2;
            uint32_t a[4][4], b[8][2];
            #pragma unroll
            for (int mi = 0; mi < 4; mi++) {
                int ar = wr * 64 + mi * 16 + q;
                a[mi][0] = As[buf][ar][kc];
                a[mi][1] = As[buf][ar + 8][kc];
                a[mi][2] = As[buf][ar][kc + 4];
                a[mi][3] = As[buf][ar + 8][kc + 4];
            }
            #pragma unroll
            for (int ni = 0; ni < 8; ni++) {
                int br = wc * 64 + ni * 8 + q;
                b[ni][0] = Bs[buf][br][kc];
                b[ni][1] = Bs[buf][br][kc + 4];
            }
            #pragma unroll
            for (int mi = 0; mi < 4; mi++)
                #pragma unroll
                for (int ni = 0; ni < 8; ni++)
                    mma16816(acc[mi][ni], a[mi], b[ni]);
        }
        __syncthreads();
    }

    const int q  = lane >> 2;
    const int cp = (lane & 3) * 2;
    #pragma unroll
    for (int mi = 0; mi < 4; mi++) {
        int r0g = row0 + wr * 64 + mi * 16 + q;
        #pragma unroll
        for (int half = 0; half < 2; half++) {
            int r = r0g + half * 8;
            if (r >= M) continue;
            if (EPI == 0) {
                float s = dinv[r];
                float* rowp = G + (size_t)r * NT + n0 + wc * 64;
                #pragma unroll
                for (int ni = 0; ni < 8; ni++) {
                    float2 v;
                    v.x = acc[mi][ni][half * 2 + 0] * s;
                    v.y = acc[mi][ni][half * 2 + 1] * s;
                    *(float2*)(rowp + ni * 8 + cp) = v;
                }
            } else {
                size_t base = (size_t)r * KP2;
                #pragma unroll
                for (int ni = 0; ni < 8; ni++) {
                    int c0 = n0 + wc * 64 + ni * 8 + cp;
                    float v0 = fmaxf(acc[mi][ni][half * 2 + 0] + bias[c0], 0.0f);
                    float v1 = fmaxf(acc[mi][ni][half * 2 + 1] + bias[c0 + 1], 0.0f);
                    __nv_bfloat16 h0 = __float2bfloat16(v0);
                    __nv_bfloat16 h1 = __float2bfloat16(v1);
                    __nv_bfloat16 l0 = __float2bfloat16(v0 - __bfloat162float(h0));
                    __nv_bfloat16 l1 = __float2bfloat16(v1 - __bfloat162float(h1));
                    __nv_bfloat162 hp; hp.x = h0; hp.y = h1;
                    __nv_bfloat162 lp; lp.x = l0; lp.y = l1;
                    *(__nv_bfloat162*)(OutB + base + c0)       = hp;
                    *(__nv_bfloat162*)(OutB + base + 256 + c0) = lp;
                    *(__nv_bfloat162*)(OutB + base + 512 + c0) = hp;
                }
            }
        }
    }
}

// ---------------- k8: layer-2 aggregation + final FC fused -----------------------
__global__ void agg2_final_kernel(const float* __restrict__ G,
                                  const float* __restrict__ b2,
                                  const float* __restrict__ Wfc,
                                  const float* __restrict__ bfc,
                                  float* __restrict__ out) {
    const int d = blockIdx.x;
    const int tid = threadIdx.x;
    const int lane = tid & 31;
    const int wid = tid >> 5;
    __shared__ int nbr[128];
    __shared__ float ws[4];

    const int beg = g_rowptr[d], end = g_rowptr[d + 1];
    float acc = G[(size_t)d * F2 + tid];
    for (int c = beg; c < end; c += 128) {
        int cnt = min(128, end - c);
        __syncthreads();
        if (tid < cnt) nbr[tid] = g_csr_src[c + tid];
        __syncthreads();
        int i = 0;
        for (; i + 8 <= cnt; i += 8) {
            float v0 = G[(size_t)nbr[i + 0] * F2 + tid];
            float v1 = G[(size_t)nbr[i + 1] * F2 + tid];
            float v2 = G[(size_t)nbr[i + 2] * F2 + tid];
            float v3 = G[(size_t)nbr[i + 3] * F2 + tid];
            float v4 = G[(size_t)nbr[i + 4] * F2 + tid];
            float v5 = G[(size_t)nbr[i + 5] * F2 + tid];
            float v6 = G[(size_t)nbr[i + 6] * F2 + tid];
            float v7 = G[(size_t)nbr[i + 7] * F2 + tid];
            acc += ((v0 + v1) + (v2 + v3)) + ((v4 + v5) + (v6 + v7));
        }
        for (; i < cnt; i++) acc += G[(size_t)nbr[i] * F2 + tid];
    }
    float h = fmaxf(g_dinv[d] * acc + b2[tid], 0.0f);
    float v = h * Wfc[tid];
    #pragma unroll
    for (int o = 16; o; o >>= 1) v += __shfl_down_sync(0xffffffffu, v, o);
    if (lane == 0) ws[wid] = v;
    __syncthreads();
    if (tid == 0) out[d] = ws[0] + ws[1] + ws[2] + ws[3] + bfc[0];
}

// ---------------- launch ----------------------------------------------------------
extern "C" void kernel_launch(void* const* d_in, const int* in_sizes, int n_in,
                              void* d_out, int out_size) {
    const float* x   = (const float*)d_in[0];
    const void*  ei  = d_in[1];
    const float* W1  = (const float*)d_in[2];
    const float* b1  = (const float*)d_in[3];
    const float* W2  = (const float*)d_in[4];
    const float* b2  = (const float*)d_in[5];
    const float* Wfc = (const float*)d_in[6];
    const float* bfc = (const float*)d_in[7];
    float*       out = (float*)d_out;

    float *dinv, *G2;
    __nv_bfloat16 *A1, *A2, *B1, *B2;
    cudaGetSymbolAddress((void**)&dinv, g_dinv);
    cudaGetSymbolAddress((void**)&G2, g_G2);
    cudaGetSymbolAddress((void**)&A1, g_A1);
    cudaGetSymbolAddress((void**)&A2, g_A2);
    cudaGetSymbolAddress((void**)&B1, g_B1);
    cudaGetSymbolAddress((void**)&B2, g_B2);

    const int SMEM = 4 * 128 * 36 * 4;  // 73728 B
    cudaFuncSetAttribute(gemm_mma_kernel<KP1, F1, 1>,
                         cudaFuncAttributeMaxDynamicSharedMemorySize, SMEM);
    cudaFuncSetAttribute(gemm_mma_kernel<KP2, F2, 0>,
                         cudaFuncAttributeMaxDynamicSharedMemorySize, SMEM);

    // k0: zero + detect + weight conversions
    {
        long long total = (long long)F1 * KP1 + (long long)F2 * KP2;  // covers NN too
        if (total < NN) total = NN;
        zero_conv_kernel<<<(unsigned)((total + 255) / 256), 256>>>(ei, W1, W2);
    }
    hist_kernel<<<(NE + 255) / 256, 256>>>(ei);
    scan_block_kernel<<<NB, 1024>>>();
    scan_add_kernel<<<(NN + 255) / 256, 256>>>();
    fill_csr_kernel<<<(NE + 255) / 256, 256>>>(ei);

    // layer 1: aggregate (dinv on the fly) then GEMM with relu+split epilogue
    aggY_kernel<<<NN, 128>>>(x);
    const int MT = (NN + 127) / 128;  // 391
    {
        dim3 grid(MT, F1 / 128);
        gemm_mma_kernel<KP1, F1, 1><<<grid, 128, SMEM>>>(A1, B1, nullptr, nullptr, b1, A2, NN);
    }

    // layer 2: GEMM (dinv epilogue) then aggregate + FC
    {
        dim3 grid(MT, F2 / 128);
        gemm_mma_kernel<KP2, F2, 0><<<grid, 128, SMEM>>>(A2, B2, dinv, G2, nullptr, nullptr, NN);
    }
    agg2_final_kernel<<<NN, 128>>>(G2, b2, Wfc, bfc, out);
}